// round 6
// baseline (speedup 1.0000x reference)
#include <cuda_runtime.h>
#include <math.h>

#define B 64
#define T 2048
#define H 512
#define S 512
#define K 128
#define V 128
#define NS 32
#define CHUNK (T/NS)        // 64 rows per CTA
#define TILE 16             // rows per smem tile
#define FTHREADS 512

// ---- scratch (no device allocations allowed) ----
__device__ float g_w[B*H];        // folded query-key weight per batch
__device__ float g_c[B];          // q . bh
__device__ float g_e[B*T];        // energies (valid t only)
__device__ float g_pm[B*NS];      // partial max
__device__ float g_ps[B*NS];      // partial masked sum S
__device__ float g_pu[B*NS*H];    // partial weighted sums
__device__ int   g_cnt[B];        // split completion counters

__device__ __forceinline__ void cp16(float* smem, const float* gmem) {
    unsigned s = (unsigned)__cvta_generic_to_shared(smem);
    asm volatile("cp.async.cg.shared.global [%0], [%1], 16;" :: "r"(s), "l"(gmem));
}

// ---------------- Kernel A: per-batch prep (q -> w, c) + counter reset ----------------
__global__ void prep_kernel(const float* __restrict__ state,
                            const float* __restrict__ Ws, const float* __restrict__ bs,
                            const float* __restrict__ bh, const float* __restrict__ Wh) {
    const int b = blockIdx.x, tid = threadIdx.x;   // 256 threads
    __shared__ float st[S];
    __shared__ float q[K];
    __shared__ float prod[K];
    st[tid]       = state[b*S + tid];
    st[tid + 256] = state[b*S + tid + 256];
    __syncthreads();
    if (tid < K) {
        const float4* wr  = (const float4*)(Ws + (size_t)tid*S);
        const float4* stv = (const float4*)st;
        float acc = 0.f;
        #pragma unroll 8
        for (int i = 0; i < S/4; i++) {
            float4 a = wr[i], x = stv[i];
            acc += a.x*x.x + a.y*x.y + a.z*x.z + a.w*x.w;
        }
        const float qq = acc + bs[tid];
        q[tid] = qq;
        prod[tid] = qq * bh[tid];
    }
    __syncthreads();
    // w: each thread two h values
    #pragma unroll
    for (int j = 0; j < H/256; j++) {
        const int h = tid + j*256;
        float acc = 0.f;
        #pragma unroll 8
        for (int k = 0; k < K; k++) acc += Wh[(size_t)k*H + h] * q[k];
        g_w[b*H + h] = acc;
    }
    if (tid == 0) {
        float c = 0.f;
        #pragma unroll 8
        for (int k = 0; k < K; k++) c += prod[k];
        g_c[b] = c;
        g_cnt[b] = 0;
    }
}

// ---------------- Kernel B: flash pass + fused last-CTA epilogue ----------------
__global__ void __launch_bounds__(FTHREADS, 3)
flash_kernel(const float* __restrict__ x, const int* __restrict__ lens,
             const float* __restrict__ Wv, const float* __restrict__ bv,
             float* __restrict__ out) {
    extern __shared__ float sm[];
    float* buf0 = sm;                    // TILE*H
    float* buf1 = sm + TILE*H;           // TILE*H
    float* wsm  = sm + 2*TILE*H;         // H (also reused as U in epilogue)
    float* esm  = wsm + H;               // TILE
    float* psm  = esm + TILE;            // TILE (also fac[NS] needs 32: use fsm)
    __shared__ float fsm[NS];
    __shared__ int   lastflag;

    const int split = blockIdx.x, b = blockIdx.y;
    const int tid = threadIdx.x;
    const int warp = tid >> 5, lane = tid & 31;

    int len = lens[b];
    if (b == 0) len = T;
    if (len > T) len = T;
    const int t0 = split * CHUNK;
    int rows = len - t0;
    if (rows > CHUNK) rows = CHUNK;
    const int pi = b*NS + split;

    if (rows > 0) {
        const int ntiles = (rows + TILE - 1) / TILE;
        const float* xb = x + (size_t)b*T*H + (size_t)t0*H;

        // prefetch tile 0 (full TILE rows; in-bounds, finite data)
        #pragma unroll
        for (int i = 0; i < (TILE*H/4)/FTHREADS; i++)
            cp16(buf0 + (tid + i*FTHREADS)*4, xb + (size_t)(tid + i*FTHREADS)*4);
        asm volatile("cp.async.commit_group;");

        wsm[tid] = g_w[b*H + tid];
        const float cb = g_c[b];

        float m = -INFINITY, Ssum = 0.f, u = 0.f;

        for (int ti = 0; ti < ntiles; ti++) {
            float* tl = (ti & 1) ? buf1 : buf0;
            if (ti + 1 < ntiles) {
                float* dst = (ti & 1) ? buf0 : buf1;
                const float* src = xb + (size_t)(ti+1)*TILE*H;
                #pragma unroll
                for (int i = 0; i < (TILE*H/4)/FTHREADS; i++)
                    cp16(dst + (tid + i*FTHREADS)*4, src + (size_t)(tid + i*FTHREADS)*4);
                asm volatile("cp.async.commit_group;");
                asm volatile("cp.async.wait_group 1;");
            } else {
                asm volatile("cp.async.wait_group 0;");
            }
            __syncthreads();

            // energy: one warp per row
            {
                const int r = warp;
                const float4* row = (const float4*)(tl + r*H);
                const float4* wv  = (const float4*)wsm;
                float acc = 0.f;
                #pragma unroll
                for (int i = 0; i < H/128; i++) {
                    float4 a = row[lane + i*32], w = wv[lane + i*32];
                    acc += a.x*w.x + a.y*w.y + a.z*w.z + a.w*w.w;
                }
                #pragma unroll
                for (int o = 16; o > 0; o >>= 1)
                    acc += __shfl_xor_sync(0xffffffffu, acc, o);
                if (lane == 0) {
                    const int t = t0 + ti*TILE + r;
                    const float e = acc + cb;
                    if (t < len) { esm[r] = e; g_e[b*T + t] = e; }
                    else         { esm[r] = -INFINITY; }
                }
            }
            __syncthreads();
            float tmax = esm[0];
            #pragma unroll
            for (int r = 1; r < TILE; r++) tmax = fmaxf(tmax, esm[r]);
            const float m_new = fmaxf(m, tmax);
            const float scale = __expf(m - m_new);
            u *= scale; Ssum *= scale;
            m = m_new;
            if (tid < TILE) psm[tid] = __expf(esm[tid] - m_new);  // exp(-inf)=0
            __syncthreads();
            #pragma unroll
            for (int r = 0; r < TILE; r++) {
                const float p = psm[r];
                Ssum += p;
                u += p * tl[r*H + tid];
            }
            __syncthreads();
        }

        g_pu[(size_t)pi*H + tid] = u;
        if (tid == 0) { g_pm[pi] = m; g_ps[pi] = Ssum; }
    } else {
        if (tid == 0) { g_pm[pi] = -INFINITY; g_ps[pi] = 0.f; }
        g_pu[(size_t)pi*H + tid] = 0.f;
    }

    // ---- last-CTA-per-batch epilogue ----
    __threadfence();
    __syncthreads();
    if (tid == 0) {
        int old = atomicAdd(&g_cnt[b], 1);
        lastflag = (old == NS - 1);
    }
    __syncthreads();
    if (!lastflag) return;
    __threadfence();

    // 1. combine scalars (replicated across threads)
    float m = -INFINITY;
    #pragma unroll
    for (int i = 0; i < NS; i++) m = fmaxf(m, g_pm[b*NS + i]);
    if (tid < NS) fsm[tid] = __expf(g_pm[b*NS + tid] - m);
    __syncthreads();
    float Ssum = 0.f;
    #pragma unroll
    for (int i = 0; i < NS; i++) Ssum += g_ps[b*NS + i] * fsm[i];
    const float coef = 1.f / Ssum;   // unmasked Z cancels (non eps-corner); Ssum > 0

    // 2. U[h] reduction (512 threads, 32 strided independent loads)
    {
        const float* pu = g_pu + (size_t)b*NS*H + tid;
        float acc = 0.f;
        #pragma unroll
        for (int i = 0; i < NS; i++) acc += pu[(size_t)i*H] * fsm[i];
        wsm[tid] = acc;   // U lives in wsm (flash done with it)
    }
    __syncthreads();

    // 3. context GEMV: 4 threads per v, quad shfl reduce
    {
        const int v = tid >> 2, quad = tid & 3;
        const float4* wr = (const float4*)(Wv + (size_t)v*H) + quad*32;
        const float4* Uv = (const float4*)wsm + quad*32;
        float acc = 0.f;
        #pragma unroll
        for (int i = 0; i < 32; i++) {
            float4 a = wr[i], xx = Uv[i];
            acc += a.x*xx.x + a.y*xx.y + a.z*xx.z + a.w*xx.w;
        }
        acc += __shfl_xor_sync(0xffffffffu, acc, 1);
        acc += __shfl_xor_sync(0xffffffffu, acc, 2);
        if (quad == 0)
            out[b*V + v] = acc * coef + bv[v] * (Ssum * coef);
    }

    // 4. attention output for this batch: 512 threads x one float4
    {
        const int t = tid * 4;
        const float4 e = ((const float4*)(g_e + (size_t)b*T))[tid];
        float4 r;
        r.x = (t + 0 < len) ? __expf(e.x - m) * coef : 0.f;
        r.y = (t + 1 < len) ? __expf(e.y - m) * coef : 0.f;
        r.z = (t + 2 < len) ? __expf(e.z - m) * coef : 0.f;
        r.w = (t + 3 < len) ? __expf(e.w - m) * coef : 0.f;
        ((float4*)(out + B*V + (size_t)b*T))[tid] = r;
    }
}

extern "C" void kernel_launch(void* const* d_in, const int* in_sizes, int n_in,
                              void* d_out, int out_size) {
    const float* state = (const float*)d_in[0];
    const float* x     = (const float*)d_in[1];  // listener_output (B,T,H)
    const int*   lens  = (const int*)  d_in[2];
    const float* Ws    = (const float*)d_in[3];
    const float* bs    = (const float*)d_in[4];
    const float* Wh    = (const float*)d_in[5];
    const float* bh    = (const float*)d_in[6];
    const float* Wv    = (const float*)d_in[7];
    const float* bv    = (const float*)d_in[8];
    float* out = (float*)d_out;

    const int smem_bytes = (2*TILE*H + H + 2*TILE) * (int)sizeof(float);  // ~66 KB
    cudaFuncSetAttribute(flash_kernel, cudaFuncAttributeMaxDynamicSharedMemorySize, smem_bytes);

    prep_kernel<<<B, 256>>>(state, Ws, bs, bh, Wh);
    dim3 grid(NS, B);
    flash_kernel<<<grid, FTHREADS, smem_bytes>>>(x, lens, Wv, bv, out);
}

// round 7
// speedup vs baseline: 1.1912x; 1.1912x over previous
#include <cuda_runtime.h>
#include <math.h>

#define B 64
#define T 2048
#define H 512
#define S 512
#define K 128
#define V 128
#define NS 64
#define CHUNK (T/NS)        // 32 rows per CTA
#define NW 8                // warps per flash CTA
#define RPW 4               // rows per warp
#define FTHREADS 256

// ---- scratch (no device allocations allowed) ----
__device__ __align__(16) float g_w[B*H];      // folded query-key weight per batch
__device__ float g_c[B];                      // q . bh
__device__ __align__(16) float g_e[B*T];      // energies (valid t only)
__device__ float g_pm[B*NS];                  // partial max
__device__ float g_ps[B*NS];                  // partial masked sum
__device__ __align__(16) float g_pu[B*NS*H];  // partial weighted sums

// ---------------- Kernel A: per-batch prep (q -> w, c) ----------------
__global__ void prep_kernel(const float* __restrict__ state,
                            const float* __restrict__ Ws, const float* __restrict__ bs,
                            const float* __restrict__ bh, const float* __restrict__ Wh) {
    const int b = blockIdx.x, tid = threadIdx.x;   // 256 threads
    __shared__ float st[S];
    __shared__ float q[K];
    __shared__ float prod[K];
    st[tid]       = state[b*S + tid];
    st[tid + 256] = state[b*S + tid + 256];
    __syncthreads();
    if (tid < K) {
        const float4* wr  = (const float4*)(Ws + (size_t)tid*S);
        const float4* stv = (const float4*)st;
        float acc = 0.f;
        #pragma unroll 8
        for (int i = 0; i < S/4; i++) {
            float4 a = wr[i], x = stv[i];
            acc += a.x*x.x + a.y*x.y + a.z*x.z + a.w*x.w;
        }
        const float qq = acc + bs[tid];
        q[tid] = qq;
        prod[tid] = qq * bh[tid];
    }
    __syncthreads();
    #pragma unroll
    for (int j = 0; j < H/256; j++) {
        const int h = tid + j*256;
        float acc = 0.f;
        #pragma unroll 8
        for (int k = 0; k < K; k++) acc += Wh[(size_t)k*H + h] * q[k];
        g_w[b*H + h] = acc;
    }
    if (tid == 0) {
        float c = 0.f;
        #pragma unroll 8
        for (int k = 0; k < K; k++) c += prod[k];
        g_c[b] = c;
    }
}

// ---------------- Kernel B: warp-autonomous flash pass ----------------
// grid (NS, B), 256 threads. Each warp: 4 rows x full H, registers only,
// no barriers in the row loop. One CTA-level combine at the end.
__global__ void __launch_bounds__(FTHREADS, 3)
flash_kernel(const float* __restrict__ x, const int* __restrict__ lens) {
    __shared__ __align__(16) float usm[NW*H];   // 16 KB
    __shared__ float msm[NW], ssm[NW];

    const int split = blockIdx.x, b = blockIdx.y;
    const int tid = threadIdx.x, warp = tid >> 5, lane = tid & 31;

    int len = lens[b];
    if (b == 0) len = T;
    if (len > T) len = T;
    const int t0 = split * CHUNK;
    const int pi = b*NS + split;
    int rows = len - t0;
    if (rows > CHUNK) rows = CHUNK;
    if (rows <= 0) {
        if (tid == 0) { g_pm[pi] = -INFINITY; g_ps[pi] = 0.f; }
        g_pu[(size_t)pi*H + tid]       = 0.f;
        g_pu[(size_t)pi*H + tid + 256] = 0.f;
        return;
    }

    const float cb = g_c[b];
    const float4* wp = (const float4*)(g_w + (size_t)b*H);
    const float4 w0 = wp[lane], w1 = wp[lane+32], w2 = wp[lane+64], w3 = wp[lane+96];

    const int rbase = t0 + warp*RPW;
    int nv = len - rbase;
    if (nv > RPW) nv = RPW;

    float m = -INFINITY, Ssum = 0.f;
    float4 u0 = {0,0,0,0}, u1 = {0,0,0,0}, u2 = {0,0,0,0}, u3 = {0,0,0,0};

    if (nv > 0) {
        const float4* xq = (const float4*)(x + (size_t)b*T*H);
        float4 c0, c1, c2, c3, n0, n1, n2, n3;
        {
            const float4* rp = xq + (size_t)rbase*(H/4);
            c0 = rp[lane]; c1 = rp[lane+32]; c2 = rp[lane+64]; c3 = rp[lane+96];
        }
        #pragma unroll
        for (int j = 0; j < RPW; j++) {
            if (j >= nv) break;
            if (j + 1 < nv) {
                const float4* rp = xq + (size_t)(rbase + j + 1)*(H/4);
                n0 = rp[lane]; n1 = rp[lane+32]; n2 = rp[lane+64]; n3 = rp[lane+96];
            }
            float d = c0.x*w0.x + c0.y*w0.y + c0.z*w0.z + c0.w*w0.w;
            d += c1.x*w1.x + c1.y*w1.y + c1.z*w1.z + c1.w*w1.w;
            d += c2.x*w2.x + c2.y*w2.y + c2.z*w2.z + c2.w*w2.w;
            d += c3.x*w3.x + c3.y*w3.y + c3.z*w3.z + c3.w*w3.w;
            #pragma unroll
            for (int o = 16; o > 0; o >>= 1)
                d += __shfl_xor_sync(0xffffffffu, d, o);
            const float e = d + cb;
            if (lane == 0) g_e[b*T + rbase + j] = e;
            const float m_new = fmaxf(m, e);
            const float sc = __expf(m - m_new);     // first iter: exp(-inf)=0
            const float p  = __expf(e - m_new);
            Ssum = Ssum*sc + p;
            u0.x = u0.x*sc + p*c0.x; u0.y = u0.y*sc + p*c0.y;
            u0.z = u0.z*sc + p*c0.z; u0.w = u0.w*sc + p*c0.w;
            u1.x = u1.x*sc + p*c1.x; u1.y = u1.y*sc + p*c1.y;
            u1.z = u1.z*sc + p*c1.z; u1.w = u1.w*sc + p*c1.w;
            u2.x = u2.x*sc + p*c2.x; u2.y = u2.y*sc + p*c2.y;
            u2.z = u2.z*sc + p*c2.z; u2.w = u2.w*sc + p*c2.w;
            u3.x = u3.x*sc + p*c3.x; u3.y = u3.y*sc + p*c3.y;
            u3.z = u3.z*sc + p*c3.z; u3.w = u3.w*sc + p*c3.w;
            m = m_new;
            c0 = n0; c1 = n1; c2 = n2; c3 = n3;
        }
    }

    if (lane == 0) { msm[warp] = m; ssm[warp] = Ssum; }
    {
        float4* uw = (float4*)(usm + warp*H);
        uw[lane] = u0; uw[lane+32] = u1; uw[lane+64] = u2; uw[lane+96] = u3;
    }
    __syncthreads();

    // CTA combine: replicated scalars + per-column reduce over NW warps
    float mg = msm[0];
    #pragma unroll
    for (int wi = 1; wi < NW; wi++) mg = fmaxf(mg, msm[wi]);
    float fac[NW];
    float Sg = 0.f;
    #pragma unroll
    for (int wi = 0; wi < NW; wi++) {
        fac[wi] = __expf(msm[wi] - mg);   // warp m=-inf -> 0 (mg finite: rows>0)
        Sg += ssm[wi] * fac[wi];
    }
    #pragma unroll
    for (int rpt = 0; rpt < 2; rpt++) {
        const int h = tid + rpt*256;
        float acc = 0.f;
        #pragma unroll
        for (int wi = 0; wi < NW; wi++) acc += usm[wi*H + h] * fac[wi];
        g_pu[(size_t)pi*H + h] = acc;
    }
    if (tid == 0) { g_pm[pi] = mg; g_ps[pi] = Sg; }
}

// ---------------- Kernel C: finale (reduce + GEMV + attention rows) ----------------
__global__ void __launch_bounds__(512) finale_kernel(const float* __restrict__ Wv,
                                                     const float* __restrict__ bv,
                                                     const int* __restrict__ lens,
                                                     float* __restrict__ out) {
    __shared__ float pmsm[NS], pssm[NS], fsm[NS];
    __shared__ __align__(16) float4 part[4*128];
    __shared__ __align__(16) float U[H];

    const int b = blockIdx.x, tid = threadIdx.x;
    if (tid < NS) { pmsm[tid] = g_pm[b*NS + tid]; pssm[tid] = g_ps[b*NS + tid]; }
    __syncthreads();
    float m = pmsm[0];
    #pragma unroll
    for (int i = 1; i < NS; i++) m = fmaxf(m, pmsm[i]);
    if (tid < NS) fsm[tid] = __expf(pmsm[tid] - m);
    __syncthreads();
    float Ssum = 0.f;
    #pragma unroll
    for (int i = 0; i < NS; i++) Ssum += pssm[i] * fsm[i];

    // U: 512 threads = 128 h-quads x 4 split-subsets, 16 independent LDG.128 each
    {
        const int hq = tid & 127, sub = tid >> 7;
        const float4* puq = (const float4*)(g_pu + (size_t)b*NS*H) + hq;
        float4 acc = {0,0,0,0};
        #pragma unroll
        for (int i = 0; i < NS/4; i++) {
            const int sp = sub*(NS/4) + i;
            const float4 v = puq[(size_t)sp*(H/4)];
            const float f = fsm[sp];
            acc.x += v.x*f; acc.y += v.y*f; acc.z += v.z*f; acc.w += v.w*f;
        }
        part[sub*128 + hq] = acc;
    }
    __syncthreads();
    if (tid < 128) {
        const float4 a0 = part[tid], a1 = part[128+tid], a2 = part[256+tid], a3 = part[384+tid];
        float4 r;
        r.x = a0.x+a1.x+a2.x+a3.x; r.y = a0.y+a1.y+a2.y+a3.y;
        r.z = a0.z+a1.z+a2.z+a3.z; r.w = a0.w+a1.w+a2.w+a3.w;
        ((float4*)U)[tid] = r;
    }
    __syncthreads();
    const float coef = 1.f / Ssum;   // unmasked Z cancels (non eps-corner); Ssum > 0

    // context GEMV: 4 threads per v, quad shfl reduce
    {
        const int v = tid >> 2, quad = tid & 3;
        const float4* wr = (const float4*)(Wv + (size_t)v*H) + quad*32;
        const float4* Uq = (const float4*)U + quad*32;
        float acc = 0.f;
        #pragma unroll
        for (int i = 0; i < 32; i++) {
            const float4 a = wr[i], xx = Uq[i];
            acc += a.x*xx.x + a.y*xx.y + a.z*xx.z + a.w*xx.w;
        }
        acc += __shfl_xor_sync(0xffffffffu, acc, 1);
        acc += __shfl_xor_sync(0xffffffffu, acc, 2);
        if (quad == 0)
            out[b*V + v] = acc * coef + bv[v] * (Ssum * coef);
    }

    // attention rows: 512 threads x one float4
    {
        int len = lens[b];
        if (b == 0) len = T;
        if (len > T) len = T;
        const int t = tid * 4;
        const float4 e = ((const float4*)(g_e + (size_t)b*T))[tid];
        float4 r;
        r.x = (t + 0 < len) ? __expf(e.x - m) * coef : 0.f;
        r.y = (t + 1 < len) ? __expf(e.y - m) * coef : 0.f;
        r.z = (t + 2 < len) ? __expf(e.z - m) * coef : 0.f;
        r.w = (t + 3 < len) ? __expf(e.w - m) * coef : 0.f;
        ((float4*)(out + B*V + (size_t)b*T))[tid] = r;
    }
}

extern "C" void kernel_launch(void* const* d_in, const int* in_sizes, int n_in,
                              void* d_out, int out_size) {
    const float* state = (const float*)d_in[0];
    const float* x     = (const float*)d_in[1];  // listener_output (B,T,H)
    const int*   lens  = (const int*)  d_in[2];
    const float* Ws    = (const float*)d_in[3];
    const float* bs    = (const float*)d_in[4];
    const float* Wh    = (const float*)d_in[5];
    const float* bh    = (const float*)d_in[6];
    const float* Wv    = (const float*)d_in[7];
    const float* bv    = (const float*)d_in[8];
    float* out = (float*)d_out;

    prep_kernel<<<B, 256>>>(state, Ws, bs, bh, Wh);
    dim3 grid(NS, B);
    flash_kernel<<<grid, FTHREADS>>>(x, lens);
    finale_kernel<<<B, 512>>>(Wv, bv, lens, out);
}

// round 10
// speedup vs baseline: 1.6002x; 1.3433x over previous
#include <cuda_runtime.h>
#include <math.h>

#define B 64
#define T 2048
#define H 512
#define S 512
#define K 128
#define V 128
#define NS 64
#define CHUNK (T/NS)        // 32 rows per CTA
#define NW 8                // warps per flash CTA
#define RPW 4               // rows per warp
#define FTHREADS 256

// ---- scratch (no device allocations allowed) ----
__device__ __align__(16) float g_q[B*K];      // query per batch
__device__ __align__(16) float g_w[B*H];      // folded query-key weight per batch
__device__ float g_c[B];                      // q . bh
__device__ __align__(16) float g_e[B*T];      // energies (valid t only)
__device__ float g_pm[B*NS];                  // partial max
__device__ float g_ps[B*NS];                  // partial masked sum
__device__ __align__(16) float g_pu[B*NS*H];  // partial weighted sums

// ---------------- Kernel A1: q[b,k] = Ws[k,:] . state[b,:] + bs[k] ----------------
// grid (B, K/8), 256 threads = 8 warps; one warp per q element.
__global__ void __launch_bounds__(256) q_kernel(const float* __restrict__ state,
                                                const float* __restrict__ Ws,
                                                const float* __restrict__ bs) {
    const int b = blockIdx.x;
    const int warp = threadIdx.x >> 5, lane = threadIdx.x & 31;
    const int k = blockIdx.y * 8 + warp;
    const float4* wr = (const float4*)(Ws + (size_t)k*S);
    const float4* sr = (const float4*)(state + (size_t)b*S);
    const float4 a0 = wr[lane],    a1 = wr[lane+32], a2 = wr[lane+64], a3 = wr[lane+96];
    const float4 x0 = sr[lane],    x1 = sr[lane+32], x2 = sr[lane+64], x3 = sr[lane+96];
    float d = a0.x*x0.x + a0.y*x0.y + a0.z*x0.z + a0.w*x0.w;
    d += a1.x*x1.x + a1.y*x1.y + a1.z*x1.z + a1.w*x1.w;
    d += a2.x*x2.x + a2.y*x2.y + a2.z*x2.z + a2.w*x2.w;
    d += a3.x*x3.x + a3.y*x3.y + a3.z*x3.z + a3.w*x3.w;
    #pragma unroll
    for (int o = 16; o > 0; o >>= 1)
        d += __shfl_xor_sync(0xffffffffu, d, o);
    if (lane == 0) g_q[b*K + k] = d + bs[k];
}

// ---------------- Kernel A2: w[b,h] = sum_k Wh[k,h] q[b,k]; c[b] = q.bh ----------------
// grid (B, 2), 256 threads; thread-per-h coalesced Wh columns.
__global__ void __launch_bounds__(256) wc_kernel(const float* __restrict__ Wh,
                                                 const float* __restrict__ bh) {
    const int b = blockIdx.x, half = blockIdx.y, tid = threadIdx.x;
    __shared__ float qs[K];
    __shared__ float red[K];
    if (tid < K) qs[tid] = g_q[b*K + tid];
    __syncthreads();
    const int h = half*256 + tid;
    float acc = 0.f;
    #pragma unroll 16
    for (int k = 0; k < K; k++) acc += Wh[(size_t)k*H + h] * qs[k];
    g_w[b*H + h] = acc;
    if (half == 0) {
        if (tid < K) red[tid] = qs[tid] * bh[tid];
        __syncthreads();
        #pragma unroll
        for (int s = K/2; s >= 32; s >>= 1) {
            if (tid < s) red[tid] += red[tid + s];
            __syncthreads();
        }
        if (tid < 32) {
            float v = red[tid];
            #pragma unroll
            for (int o = 16; o > 0; o >>= 1)
                v += __shfl_xor_sync(0xffffffffu, v, o);
            if (tid == 0) g_c[b] = v;
        }
    }
}

// ---------------- Kernel B: warp-autonomous flash pass ----------------
__global__ void __launch_bounds__(FTHREADS, 3)
flash_kernel(const float* __restrict__ x, const int* __restrict__ lens) {
    __shared__ __align__(16) float usm[NW*H];   // 16 KB
    __shared__ float msm[NW], ssm[NW];

    const int split = blockIdx.x, b = blockIdx.y;
    const int tid = threadIdx.x, warp = tid >> 5, lane = tid & 31;

    int len = lens[b];
    if (b == 0) len = T;
    if (len > T) len = T;
    const int t0 = split * CHUNK;
    const int pi = b*NS + split;
    int rows = len - t0;
    if (rows > CHUNK) rows = CHUNK;
    if (rows <= 0) {
        if (tid == 0) { g_pm[pi] = -INFINITY; g_ps[pi] = 0.f; }
        g_pu[(size_t)pi*H + tid]       = 0.f;
        g_pu[(size_t)pi*H + tid + 256] = 0.f;
        return;
    }

    const float cb = g_c[b];
    const float4* wp = (const float4*)(g_w + (size_t)b*H);
    const float4 w0 = wp[lane], w1 = wp[lane+32], w2 = wp[lane+64], w3 = wp[lane+96];

    const int rbase = t0 + warp*RPW;
    int nv = len - rbase;
    if (nv > RPW) nv = RPW;

    float m = -INFINITY, Ssum = 0.f;
    float4 u0 = {0,0,0,0}, u1 = {0,0,0,0}, u2 = {0,0,0,0}, u3 = {0,0,0,0};

    if (nv > 0) {
        const float4* xq = (const float4*)(x + (size_t)b*T*H);
        float4 c0, c1, c2, c3, n0, n1, n2, n3;
        {
            const float4* rp = xq + (size_t)rbase*(H/4);
            c0 = rp[lane]; c1 = rp[lane+32]; c2 = rp[lane+64]; c3 = rp[lane+96];
        }
        #pragma unroll
        for (int j = 0; j < RPW; j++) {
            if (j >= nv) break;
            if (j + 1 < nv) {
                const float4* rp = xq + (size_t)(rbase + j + 1)*(H/4);
                n0 = rp[lane]; n1 = rp[lane+32]; n2 = rp[lane+64]; n3 = rp[lane+96];
            }
            float d = c0.x*w0.x + c0.y*w0.y + c0.z*w0.z + c0.w*w0.w;
            d += c1.x*w1.x + c1.y*w1.y + c1.z*w1.z + c1.w*w1.w;
            d += c2.x*w2.x + c2.y*w2.y + c2.z*w2.z + c2.w*w2.w;
            d += c3.x*w3.x + c3.y*w3.y + c3.z*w3.z + c3.w*w3.w;
            #pragma unroll
            for (int o = 16; o > 0; o >>= 1)
                d += __shfl_xor_sync(0xffffffffu, d, o);
            const float e = d + cb;
            if (lane == 0) g_e[b*T + rbase + j] = e;
            const float m_new = fmaxf(m, e);
            const float sc = __expf(m - m_new);     // first iter: exp(-inf)=0
            const float p  = __expf(e - m_new);
            Ssum = Ssum*sc + p;
            u0.x = u0.x*sc + p*c0.x; u0.y = u0.y*sc + p*c0.y;
            u0.z = u0.z*sc + p*c0.z; u0.w = u0.w*sc + p*c0.w;
            u1.x = u1.x*sc + p*c1.x; u1.y = u1.y*sc + p*c1.y;
            u1.z = u1.z*sc + p*c1.z; u1.w = u1.w*sc + p*c1.w;
            u2.x = u2.x*sc + p*c2.x; u2.y = u2.y*sc + p*c2.y;
            u2.z = u2.z*sc + p*c2.z; u2.w = u2.w*sc + p*c2.w;
            u3.x = u3.x*sc + p*c3.x; u3.y = u3.y*sc + p*c3.y;
            u3.z = u3.z*sc + p*c3.z; u3.w = u3.w*sc + p*c3.w;
            m = m_new;
            c0 = n0; c1 = n1; c2 = n2; c3 = n3;
        }
    }

    if (lane == 0) { msm[warp] = m; ssm[warp] = Ssum; }
    {
        float4* uw = (float4*)(usm + warp*H);
        uw[lane] = u0; uw[lane+32] = u1; uw[lane+64] = u2; uw[lane+96] = u3;
    }
    __syncthreads();

    float mg = msm[0];
    #pragma unroll
    for (int wi = 1; wi < NW; wi++) mg = fmaxf(mg, msm[wi]);
    float fac[NW];
    float Sg = 0.f;
    #pragma unroll
    for (int wi = 0; wi < NW; wi++) {
        fac[wi] = __expf(msm[wi] - mg);   // warp m=-inf -> 0 (mg finite: rows>0)
        Sg += ssm[wi] * fac[wi];
    }
    #pragma unroll
    for (int rpt = 0; rpt < 2; rpt++) {
        const int h = tid + rpt*256;
        float acc = 0.f;
        #pragma unroll
        for (int wi = 0; wi < NW; wi++) acc += usm[wi*H + h] * fac[wi];
        g_pu[(size_t)pi*H + h] = acc;
    }
    if (tid == 0) { g_pm[pi] = mg; g_ps[pi] = Sg; }
}

// ---------------- Kernel C: finale (reduce + GEMV + attention rows) ----------------
__global__ void __launch_bounds__(512) finale_kernel(const float* __restrict__ Wv,
                                                     const float* __restrict__ bv,
                                                     const int* __restrict__ lens,
                                                     float* __restrict__ out) {
    __shared__ float pmsm[NS], pssm[NS], fsm[NS];
    __shared__ __align__(16) float4 part[4*128];
    __shared__ __align__(16) float U[H];

    const int b = blockIdx.x, tid = threadIdx.x;
    if (tid < NS) { pmsm[tid] = g_pm[b*NS + tid]; pssm[tid] = g_ps[b*NS + tid]; }
    __syncthreads();
    float m = pmsm[0];
    #pragma unroll
    for (int i = 1; i < NS; i++) m = fmaxf(m, pmsm[i]);
    if (tid < NS) fsm[tid] = __expf(pmsm[tid] - m);
    __syncthreads();
    float Ssum = 0.f;
    #pragma unroll
    for (int i = 0; i < NS; i++) Ssum += pssm[i] * fsm[i];

    {
        const int hq = tid & 127, sub = tid >> 7;
        const float4* puq = (const float4*)(g_pu + (size_t)b*NS*H) + hq;
        float4 acc = {0,0,0,0};
        #pragma unroll
        for (int i = 0; i < NS/4; i++) {
            const int sp = sub*(NS/4) + i;
            const float4 v = puq[(size_t)sp*(H/4)];
            const float f = fsm[sp];
            acc.x += v.x*f; acc.y += v.y*f; acc.z += v.z*f; acc.w += v.w*f;
        }
        part[sub*128 + hq] = acc;
    }
    __syncthreads();
    if (tid < 128) {
        const float4 a0 = part[tid], a1 = part[128+tid], a2 = part[256+tid], a3 = part[384+tid];
        float4 r;
        r.x = a0.x+a1.x+a2.x+a3.x; r.y = a0.y+a1.y+a2.y+a3.y;
        r.z = a0.z+a1.z+a2.z+a3.z; r.w = a0.w+a1.w+a2.w+a3.w;
        ((float4*)U)[tid] = r;
    }
    __syncthreads();
    const float coef = 1.f / Ssum;   // unmasked Z cancels (non eps-corner); Ssum > 0

    {
        const int v = tid >> 2, quad = tid & 3;
        const float4* wr = (const float4*)(Wv + (size_t)v*H) + quad*32;
        const float4* Uq = (const float4*)U + quad*32;
        float acc = 0.f;
        #pragma unroll
        for (int i = 0; i < 32; i++) {
            const float4 a = wr[i], xx = Uq[i];
            acc += a.x*xx.x + a.y*xx.y + a.z*xx.z + a.w*xx.w;
        }
        acc += __shfl_xor_sync(0xffffffffu, acc, 1);
        acc += __shfl_xor_sync(0xffffffffu, acc, 2);
        if (quad == 0)
            out[b*V + v] = acc * coef + bv[v] * (Ssum * coef);
    }

    {
        int len = lens[b];
        if (b == 0) len = T;
        if (len > T) len = T;
        const int t = tid * 4;
        const float4 e = ((const float4*)(g_e + (size_t)b*T))[tid];
        float4 r;
        r.x = (t + 0 < len) ? __expf(e.x - m) * coef : 0.f;
        r.y = (t + 1 < len) ? __expf(e.y - m) * coef : 0.f;
        r.z = (t + 2 < len) ? __expf(e.z - m) * coef : 0.f;
        r.w = (t + 3 < len) ? __expf(e.w - m) * coef : 0.f;
        ((float4*)(out + B*V + (size_t)b*T))[tid] = r;
    }
}

extern "C" void kernel_launch(void* const* d_in, const int* in_sizes, int n_in,
                              void* d_out, int out_size) {
    const float* state = (const float*)d_in[0];
    const float* x     = (const float*)d_in[1];  // listener_output (B,T,H)
    const int*   lens  = (const int*)  d_in[2];
    const float* Ws    = (const float*)d_in[3];
    const float* bs    = (const float*)d_in[4];
    const float* Wh    = (const float*)d_in[5];
    const float* bh    = (const float*)d_in[6];
    const float* Wv    = (const float*)d_in[7];
    const float* bv    = (const float*)d_in[8];
    float* out = (float*)d_out;

    dim3 gq(B, K/8);
    q_kernel<<<gq, 256>>>(state, Ws, bs);
    dim3 gwc(B, 2);
    wc_kernel<<<gwc, 256>>>(Wh, bh);
    dim3 grid(NS, B);
    flash_kernel<<<grid, FTHREADS>>>(x, lens);
    finale_kernel<<<B, 512>>>(Wv, bv, lens, out);
}